// round 13
// baseline (speedup 1.0000x reference)
#include <cuda_runtime.h>
#include <cuda_bf16.h>
#include <cstdint>

#define N_NEURONS 4096
#define N_EDGES   131072
#define VOCAB     8192
#define BB        8
#define TT        128
#define NB        (N_NEURONS*BB)
#define DECAYF    0.99f

#define RBLK   128
#define RTHR   1024
#define NWARPS 32
#define CAP    2048
#define MAXB   128
#define NGENW  16

/* ------------------ static device scratch ------------------ */
__device__ float g_Xall[TT*NB];
__device__ float g_xs  [TT*NB];
__device__ float g_S   [N_NEURONS*16];           /* x: +0..7, y: +8..15 */
__device__ float g_A[NB];
__device__ int   g_perm [N_EDGES];
__device__ int   g_counts[N_NEURONS];
__device__ int   g_cursor[N_NEURONS];
__device__ int   g_rowptr[N_NEURONS+1];
__device__ __nv_bfloat16 g_Ahi[BB*TT*N_NEURONS];
__device__ __nv_bfloat16 g_Alo[BB*TT*N_NEURONS];
__device__ __nv_bfloat16 g_Whi[VOCAB*N_NEURONS];
__device__ __nv_bfloat16 g_Wlo[VOCAB*N_NEURONS];

__device__ unsigned g_cnt = 0;
__device__ unsigned g_genw[NGENW*32];            /* 16 gen words, 128B apart */

__device__ __forceinline__ uint32_t smem_u32(const void* p) {
    uint32_t a;
    asm("{ .reg .u64 t; cvta.to.shared.u64 t, %1; cvt.u32.u64 %0, t; }" : "=r"(a) : "l"(p));
    return a;
}

/* ------------------ CSR preprocessing ------------------ */
__global__ void k_hist(const int* __restrict__ dst) {
    int e = blockIdx.x*blockDim.x + threadIdx.x;
    if (e < N_EDGES) atomicAdd(&g_counts[dst[e]], 1);
}
__global__ void k_scan() {
    __shared__ int sh[1024];
    int tid = threadIdx.x, base = tid*4;
    int v0 = g_counts[base+0], v1 = g_counts[base+1];
    int v2 = g_counts[base+2], v3 = g_counts[base+3];
    int s = v0+v1+v2+v3;
    sh[tid] = s; __syncthreads();
    for (int off = 1; off < 1024; off <<= 1) {
        int t = (tid >= off) ? sh[tid-off] : 0;
        __syncthreads(); sh[tid] += t; __syncthreads();
    }
    int excl = sh[tid] - s;
    g_rowptr[base+0] = excl; g_cursor[base+0] = excl; excl += v0;
    g_rowptr[base+1] = excl; g_cursor[base+1] = excl; excl += v1;
    g_rowptr[base+2] = excl; g_cursor[base+2] = excl; excl += v2;
    g_rowptr[base+3] = excl; g_cursor[base+3] = excl; excl += v3;
    if (tid == 1023) g_rowptr[N_NEURONS] = excl;
    g_counts[base+0]=0; g_counts[base+1]=0; g_counts[base+2]=0; g_counts[base+3]=0;
}
__global__ void k_scatter(const int* __restrict__ dst) {
    int e = blockIdx.x*blockDim.x + threadIdx.x;
    if (e < N_EDGES) { int p = atomicAdd(&g_cursor[dst[e]], 1); g_perm[p] = e; }
}

/* ------------------ W bf16 split ------------------ */
__global__ void k_convW(const float* __restrict__ W) {
    int i = blockIdx.x*blockDim.x + threadIdx.x;
    if (i >= VOCAB*N_NEURONS/4) return;
    float4 w = ((const float4*)W)[i];
    __nv_bfloat16 h[4], l[4];
    float v[4] = {w.x, w.y, w.z, w.w};
#pragma unroll
    for (int k = 0; k < 4; k++) {
        h[k] = __float2bfloat16_rn(v[k]);
        l[k] = __float2bfloat16_rn(v[k] - __bfloat162float(h[k]));
    }
    ((ushort4*)g_Whi)[i] = *(ushort4*)h;
    ((ushort4*)g_Wlo)[i] = *(ushort4*)l;
}

/* ------------------ grid barrier: counter arrival + 16-way fan-out release */
__device__ __forceinline__ void gbar(unsigned target) {
    __syncthreads();
    if (threadIdx.x == 0) {
        unsigned prev;
        asm volatile("atom.global.acq_rel.gpu.add.u32 %0, [%1], 1;"
                     : "=r"(prev) : "l"(&g_cnt) : "memory");
        if (prev == (unsigned)(RBLK-1)) {
            unsigned z = 0;
            asm volatile("st.global.relaxed.gpu.u32 [%0], %1;" :: "l"(&g_cnt), "r"(z) : "memory");
#pragma unroll
            for (int w = 0; w < NGENW; w++)
                asm volatile("st.global.release.gpu.u32 [%0], %1;"
                             :: "l"(&g_genw[w*32]), "r"(target) : "memory");
        } else {
            unsigned* wp = &g_genw[(blockIdx.x & (NGENW-1))*32];
            unsigned v;
            do {
                asm volatile("ld.global.acquire.gpu.u32 %0, [%1];" : "=r"(v) : "l"(wp) : "memory");
            } while (v < target);
        }
    }
    __syncthreads();
}

/* reset barrier state so graph replays start clean */
__global__ void k_rstbar() {
    if (threadIdx.x < NGENW*32) g_genw[threadIdx.x] = 0;
    if (threadIdx.x == 0) g_cnt = 0;
}

__device__ __forceinline__ void bfly4(float4& a) {
#pragma unroll
    for (int d = 2; d < 32; d <<= 1) {
        a.x += __shfl_xor_sync(0xffffffffu, a.x, d);
        a.y += __shfl_xor_sync(0xffffffffu, a.y, d);
        a.z += __shfl_xor_sync(0xffffffffu, a.z, d);
        a.w += __shfl_xor_sync(0xffffffffu, a.w, d);
    }
}

__global__ void __launch_bounds__(RTHR) k_recurrent(
        const int* __restrict__ idx, const float* __restrict__ Wemb,
        const int* __restrict__ srcA, const float* __restrict__ GxA,
        const float* __restrict__ GyA, const float* __restrict__ GsA,
        float* __restrict__ sig_out)
{
    __shared__ int   s_n[CAP];
    __shared__ float s_gs[CAP], s_gx[CAP], s_gy[CAP], s_sig[CAP];
    __shared__ int   s_wcnt[NWARPS], s_wbase[NWARPS+1];

    const int tid  = threadIdx.x;
    const int wid  = tid >> 5;
    const int lane = tid & 31;
    const int nrn  = blockIdx.x*NWARPS + wid;
    const int h    = lane & 1;
    const int es   = lane >> 1;
    const int gtid = blockIdx.x*RTHR + tid;
    unsigned bar = 0;

    /* embed */
    for (int id = gtid; id < TT*N_NEURONS; id += RBLK*RTHR) {
        int t = id >> 12, n = id & (N_NEURONS-1);
        float v[8];
#pragma unroll
        for (int bb = 0; bb < 8; bb++)
            v[bb] = Wemb[(size_t)idx[bb*TT + t]*N_NEURONS + n];
        float4* o = (float4*)&g_Xall[(size_t)id*8];
        o[0] = make_float4(v[0], v[1], v[2], v[3]);
        o[1] = make_float4(v[4], v[5], v[6], v[7]);
    }

    /* stage edges (padded to 32 per neuron) */
    const int grs = g_rowptr[nrn];
    const int cnt = g_rowptr[nrn+1] - grs;
    const int pc  = (cnt + 31) & ~31;
    if (lane == 0) s_wcnt[wid] = pc;
    __syncthreads();
    if (tid == 0) {
        int acc = 0;
        for (int w = 0; w < NWARPS; w++) { s_wbase[w] = acc; acc += s_wcnt[w]; }
        s_wbase[NWARPS] = acc;
    }
    __syncthreads();
    const int lb = s_wbase[wid];

    if (lane == 0) {
        int lbuf[MAXB];
        for (int j = 0; j < cnt; j++) lbuf[j] = g_perm[grs + j];
        for (int i = 1; i < cnt; i++) {
            int key = lbuf[i], j = i-1;
            while (j >= 0 && lbuf[j] > key) { lbuf[j+1] = lbuf[j]; j--; }
            lbuf[j+1] = key;
        }
        for (int j = 0; j < cnt; j++) s_n[lb + j] = lbuf[j];
    }
    __syncwarp();
    for (int j = lane; j < pc; j += 32) {
        int pos = lb + j;
        if (j < cnt) {
            int e = s_n[pos];
            g_perm[grs + j] = e;
            s_n[pos]  = srcA[e];
            s_gs[pos] = GsA[e];
            s_gx[pos] = GxA[e];
            s_gy[pos] = GyA[e];
        } else {
            s_n[pos] = 0; s_gs[pos] = 0.f; s_gx[pos] = 0.f; s_gy[pos] = 0.f;
        }
        s_sig[pos] = 0.0f;
    }
    gbar(++bar);

    /* y0 = X[:,0,:] */
    if (lane < 2)
        *(float4*)&g_S[nrn*16 + 8 + h*4] = *(const float4*)&g_Xall[nrn*8 + h*4];
    gbar(++bar);

    for (int t = 0; t < TT; t++) {
        const float* Xt = g_Xall + (size_t)t*NB;
        for (int layer = 0; layer < 2; layer++) {
            const float* xbase = (layer == 0) ? Xt : g_S;
            const int    xstr  = (layer == 0) ? 8 : 16;
            /* pass1 */
            {
                float4 xn4 = *(const float4*)(xbase + (size_t)nrn*xstr + h*4);
                float4 acc = make_float4(0.f, 0.f, 0.f, 0.f);
                for (int j0 = 0; j0 < pc; j0 += 16) {
                    int   slot = lb + j0 + es;
                    int   ns   = s_n[slot];
                    float sg   = s_sig[slot];
                    float4 xs4 = *(const float4*)(xbase + (size_t)ns*xstr + h*4);
                    float4 ys4 = *(const float4*)(&g_S[ns*16 + 8 + h*4]);
                    float p = ys4.x*xn4.x + ys4.y*xn4.y + ys4.z*xn4.z + ys4.w*xn4.w;
                    p += __shfl_xor_sync(0xffffffffu, p, 1);
                    acc.x += xs4.x*sg; acc.y += xs4.y*sg;
                    acc.z += xs4.z*sg; acc.w += xs4.w*sg;
                    if (h == 0)
                        s_sig[slot] = fmaf(p*0.125f, s_gs[slot], sg) * DECAYF;
                }
                bfly4(acc);
                if (lane < 2) *(float4*)&g_A[nrn*8 + h*4] = acc;
            }
            gbar(++bar);
            /* pass2 */
            {
                float4 acc = make_float4(0.f, 0.f, 0.f, 0.f);
                for (int j0 = 0; j0 < pc; j0 += 16) {
                    int   slot = lb + j0 + es;
                    int   ns   = s_n[slot];
                    float gy   = s_gy[slot];
                    float4 a4  = *(const float4*)(&g_A[ns*8 + h*4]);
                    a4.x = a4.x > 0.f ? a4.x : 0.f;  a4.y = a4.y > 0.f ? a4.y : 0.f;
                    a4.z = a4.z > 0.f ? a4.z : 0.f;  a4.w = a4.w > 0.f ? a4.w : 0.f;
                    acc.x += a4.x*gy; acc.y += a4.y*gy;
                    acc.z += a4.z*gy; acc.w += a4.w*gy;
                }
                bfly4(acc);
                if (lane < 2) *(float4*)&g_S[nrn*16 + 8 + h*4] = acc;
            }
            gbar(++bar);
            /* pass3 */
            {
                float4 acc = make_float4(0.f, 0.f, 0.f, 0.f);
                for (int j0 = 0; j0 < pc; j0 += 16) {
                    int   slot = lb + j0 + es;
                    int   ns   = s_n[slot];
                    float gx   = s_gx[slot];
                    float4 y4  = *(const float4*)(&g_S[ns*16 + 8 + h*4]);
                    acc.x += y4.x*gx; acc.y += y4.y*gx;
                    acc.z += y4.z*gx; acc.w += y4.w*gx;
                }
                bfly4(acc);
                if (lane < 2) {
                    acc.x = acc.x > 0.f ? acc.x : 0.f;  acc.y = acc.y > 0.f ? acc.y : 0.f;
                    acc.z = acc.z > 0.f ? acc.z : 0.f;  acc.w = acc.w > 0.f ? acc.w : 0.f;
                    if (layer == 0) *(float4*)&g_S[nrn*16 + h*4] = acc;
                    else            *(float4*)&g_xs[(size_t)t*NB + nrn*8 + h*4] = acc;
                }
            }
            if (layer == 0) gbar(++bar);
        }
    }

    if (sig_out)
        for (int j = lane; j < cnt; j += 32)
            sig_out[g_perm[grs + j]] = s_sig[lb + j];
}

/* ------------------ transpose + bf16 split of activations ------------------ */
__global__ void k_transpose() {
    int id = blockIdx.x*blockDim.x + threadIdx.x;
    if (id >= TT*N_NEURONS) return;
    int t = id >> 12, n = id & (N_NEURONS-1);
    const float4* p = (const float4*)&g_xs[(size_t)id*8];
    float4 v0 = p[0], v1 = p[1];
    float v[8] = {v0.x, v0.y, v0.z, v0.w, v1.x, v1.y, v1.z, v1.w};
#pragma unroll
    for (int bb = 0; bb < 8; bb++) {
        size_t o = (size_t)(bb*TT + t)*N_NEURONS + n;
        __nv_bfloat16 hh = __float2bfloat16_rn(v[bb]);
        g_Ahi[o] = hh;
        g_Alo[o] = __float2bfloat16_rn(v[bb] - __bfloat162float(hh));
    }
}

/* ------------------ mma.sync bf16 GEMM: 128x256 tile, warp 64x64 ----------- */
#define APITCH 40
#define ASTGB  (128*APITCH*2)
#define BSTGB  (256*APITCH*2)
#define NSTG   3
#define SMEM_GEMM (NSTG*(ASTGB + BSTGB))
#define NSTAGES_TOT 384

#define LDM4(r, a) asm volatile( \
    "ldmatrix.sync.aligned.m8n8.x4.shared.b16 {%0,%1,%2,%3}, [%4];" \
    : "=r"((r)[0]), "=r"((r)[1]), "=r"((r)[2]), "=r"((r)[3]) : "r"(a))

#define MMA16816(d, a, b0r, b1r) asm volatile( \
    "mma.sync.aligned.m16n8k16.row.col.f32.bf16.bf16.f32 " \
    "{%0,%1,%2,%3},{%4,%5,%6,%7},{%8,%9},{%0,%1,%2,%3};" \
    : "+f"((d)[0]), "+f"((d)[1]), "+f"((d)[2]), "+f"((d)[3]) \
    : "r"((a)[0]), "r"((a)[1]), "r"((a)[2]), "r"((a)[3]), "r"(b0r), "r"(b1r))

__global__ void __launch_bounds__(256, 1) k_gemm_mma(const float* __restrict__ bias,
                                                     float* __restrict__ out)
{
    extern __shared__ char smem[];
    const uint32_t sA = smem_u32(smem);
    const uint32_t sB = sA + NSTG*ASTGB;
    const int tid  = threadIdx.x;
    const int wid  = tid >> 5;
    const int lane = tid & 31;
    const int wm = wid & 1, wn = wid >> 1;
    const int m0 = blockIdx.x * 128;
    const int n0 = blockIdx.y * 256;

    float acc[4][8][4];
#pragma unroll
    for (int i = 0; i < 4; i++)
#pragma unroll
        for (int j = 0; j < 8; j++)
#pragma unroll
            for (int k = 0; k < 4; k++) acc[i][j][k] = 0.0f;

    auto load_stage = [&](int gs, int slot) {
        int seg = gs >> 7;
        int k0  = (gs & 127) << 5;
        const __nv_bfloat16* Ap = (seg == 1) ? g_Alo : g_Ahi;
        const __nv_bfloat16* Bp = (seg == 2) ? g_Wlo : g_Whi;
#pragma unroll
        for (int i = tid; i < 1536; i += 256) {
            if (i < 512) {
                int row = i >> 2, ch = i & 3;
                uint32_t da = sA + slot*ASTGB + (row*APITCH + ch*8)*2;
                const __nv_bfloat16* ga = Ap + (size_t)(m0 + row)*N_NEURONS + k0 + ch*8;
                asm volatile("cp.async.cg.shared.global [%0], [%1], 16;" :: "r"(da), "l"(ga) : "memory");
            } else {
                int i2 = i - 512;
                int row = i2 >> 2, ch = i2 & 3;
                uint32_t db = sB + slot*BSTGB + (row*APITCH + ch*8)*2;
                const __nv_bfloat16* gb = Bp + (size_t)(n0 + row)*N_NEURONS + k0 + ch*8;
                asm volatile("cp.async.cg.shared.global [%0], [%1], 16;" :: "r"(db), "l"(gb) : "memory");
            }
        }
        asm volatile("cp.async.commit_group;" ::: "memory");
    };

    load_stage(0, 0);
    load_stage(1, 1);

    for (int it = 0; it < NSTAGES_TOT; it++) {
        if (it + 2 < NSTAGES_TOT)
            asm volatile("cp.async.wait_group 1;" ::: "memory");
        else
            asm volatile("cp.async.wait_group 0;" ::: "memory");
        __syncthreads();
        if (it + 2 < NSTAGES_TOT)
            load_stage(it + 2, (it + 2) % NSTG);

        int slot = it % NSTG;
        uint32_t aB = sA + slot*ASTGB;
        uint32_t bB = sB + slot*BSTGB;
#pragma unroll
        for (int kk = 0; kk < 2; kk++) {
            uint32_t af[4][4], bf[4][4];
#pragma unroll
            for (int mi = 0; mi < 4; mi++) {
                uint32_t addr = aB + (uint32_t)(((wm*64 + mi*16 + (lane & 15))*APITCH
                                 + kk*16 + (lane >> 4)*8) * 2);
                LDM4(af[mi], addr);
            }
#pragma unroll
            for (int nh = 0; nh < 4; nh++) {
                int mat = lane >> 3;
                uint32_t addr = bB + (uint32_t)(((wn*64 + nh*16 + (lane & 7) + (mat >> 1)*8)*APITCH
                                 + kk*16 + (mat & 1)*8) * 2);
                LDM4(bf[nh], addr);
            }
#pragma unroll
            for (int mi = 0; mi < 4; mi++)
#pragma unroll
                for (int ni = 0; ni < 8; ni++)
                    MMA16816(acc[mi][ni], af[mi], bf[ni >> 1][(ni & 1)*2], bf[ni >> 1][(ni & 1)*2 + 1]);
        }
    }

    const int mb = m0 + wm*64;
    const int nb = n0 + wn*64;
#pragma unroll
    for (int ni = 0; ni < 8; ni++) {
        int c0 = nb + ni*8 + (lane & 3)*2;
        float bv0 = bias[c0], bv1 = bias[c0 + 1];
#pragma unroll
        for (int mi = 0; mi < 4; mi++) {
            int r0 = mb + mi*16 + (lane >> 2);
            float2 v0 = make_float2(acc[mi][ni][0] + bv0, acc[mi][ni][1] + bv1);
            float2 v1 = make_float2(acc[mi][ni][2] + bv0, acc[mi][ni][3] + bv1);
            *(float2*)&out[(size_t)r0*VOCAB + c0]       = v0;
            *(float2*)&out[(size_t)(r0 + 8)*VOCAB + c0] = v1;
        }
    }
}

/* ------------------ launch ------------------ */
extern "C" void kernel_launch(void* const* d_in, const int* in_sizes, int n_in,
                              void* d_out, int out_size) {
    const int*   idx  = (const int*)  d_in[0];
    const int*   src  = (const int*)  d_in[1];
    const int*   dst  = (const int*)  d_in[2];
    const float* Wemb = (const float*)d_in[3];
    const float* Gx   = (const float*)d_in[4];
    const float* Gy   = (const float*)d_in[5];
    const float* Gs   = (const float*)d_in[6];
    const float* Wout = (const float*)d_in[7];
    const float* bout = (const float*)d_in[8];
    float* out = (float*)d_out;

    long long btv = (long long)BB*TT*VOCAB;
    float* sig_out = ((long long)out_size >= btv + N_EDGES) ? (out + btv) : nullptr;

    static int smem_set = 0;
    if (!smem_set) {
        cudaFuncSetAttribute(k_gemm_mma, cudaFuncAttributeMaxDynamicSharedMemorySize, SMEM_GEMM);
        smem_set = 1;
    }

    k_hist   <<<512, 256>>>(dst);
    k_scan   <<<1, 1024>>>();
    k_scatter<<<512, 256>>>(dst);
    k_recurrent<<<RBLK, RTHR>>>(idx, Wemb, src, Gx, Gy, Gs, sig_out);  /* 4th: profiled */
    k_rstbar <<<1, 512>>>();
    k_convW  <<<(VOCAB*N_NEURONS/4 + 255)/256, 256>>>(Wout);
    k_transpose<<<(TT*N_NEURONS)/256, 256>>>();
    dim3 gg(BB*TT/128, VOCAB/256);
    k_gemm_mma<<<gg, 256, SMEM_GEMM>>>(bout, out);
}

// round 15
// speedup vs baseline: 1.7823x; 1.7823x over previous
#include <cuda_runtime.h>
#include <cuda_bf16.h>
#include <cstdint>

#define N_NEURONS 4096
#define N_EDGES   131072
#define VOCAB     8192
#define BB        8
#define TT        128
#define NB        (N_NEURONS*BB)
#define DECAYF    0.99f

#define RBLK   128
#define RTHR   512
#define NWARPS 16
#define NPW    2
#define CAP    2048
#define MAXB   128

/* ------------------ static device scratch ------------------ */
__device__ float g_Xall[TT*NB];
__device__ float g_xs  [TT*NB];
__device__ float g_S   [N_NEURONS*16];           /* x: +0..7, y: +8..15 */
__device__ float g_A[NB];
__device__ int   g_perm [N_EDGES];
__device__ int   g_counts[N_NEURONS];
__device__ int   g_cursor[N_NEURONS];
__device__ int   g_rowptr[N_NEURONS+1];
__device__ __nv_bfloat16 g_Ahi[BB*TT*N_NEURONS];
__device__ __nv_bfloat16 g_Alo[BB*TT*N_NEURONS];
__device__ __nv_bfloat16 g_Whi[VOCAB*N_NEURONS];
__device__ __nv_bfloat16 g_Wlo[VOCAB*N_NEURONS];

__device__ unsigned g_cnt = 0;
__device__ unsigned g_gen = 0;

__device__ __forceinline__ uint32_t smem_u32(const void* p) {
    uint32_t a;
    asm("{ .reg .u64 t; cvta.to.shared.u64 t, %1; cvt.u32.u64 %0, t; }" : "=r"(a) : "l"(p));
    return a;
}

/* ------------------ CSR preprocessing ------------------ */
__global__ void k_hist(const int* __restrict__ dst) {
    int e = blockIdx.x*blockDim.x + threadIdx.x;
    if (e < N_EDGES) atomicAdd(&g_counts[dst[e]], 1);
}
__global__ void k_scan() {
    __shared__ int sh[1024];
    int tid = threadIdx.x, base = tid*4;
    int v0 = g_counts[base+0], v1 = g_counts[base+1];
    int v2 = g_counts[base+2], v3 = g_counts[base+3];
    int s = v0+v1+v2+v3;
    sh[tid] = s; __syncthreads();
    for (int off = 1; off < 1024; off <<= 1) {
        int t = (tid >= off) ? sh[tid-off] : 0;
        __syncthreads(); sh[tid] += t; __syncthreads();
    }
    int excl = sh[tid] - s;
    g_rowptr[base+0] = excl; g_cursor[base+0] = excl; excl += v0;
    g_rowptr[base+1] = excl; g_cursor[base+1] = excl; excl += v1;
    g_rowptr[base+2] = excl; g_cursor[base+2] = excl; excl += v2;
    g_rowptr[base+3] = excl; g_cursor[base+3] = excl; excl += v3;
    if (tid == 1023) g_rowptr[N_NEURONS] = excl;
    g_counts[base+0]=0; g_counts[base+1]=0; g_counts[base+2]=0; g_counts[base+3]=0;
}
__global__ void k_scatter(const int* __restrict__ dst) {
    int e = blockIdx.x*blockDim.x + threadIdx.x;
    if (e < N_EDGES) { int p = atomicAdd(&g_cursor[dst[e]], 1); g_perm[p] = e; }
}

/* ------------------ W bf16 split ------------------ */
__global__ void k_convW(const float* __restrict__ W) {
    int i = blockIdx.x*blockDim.x + threadIdx.x;
    if (i >= VOCAB*N_NEURONS/4) return;
    float4 w = ((const float4*)W)[i];
    __nv_bfloat16 h[4], l[4];
    float v[4] = {w.x, w.y, w.z, w.w};
#pragma unroll
    for (int k = 0; k < 4; k++) {
        h[k] = __float2bfloat16_rn(v[k]);
        l[k] = __float2bfloat16_rn(v[k] - __bfloat162float(h[k]));
    }
    ((ushort4*)g_Whi)[i] = *(ushort4*)h;
    ((ushort4*)g_Wlo)[i] = *(ushort4*)l;
}

/* ------------------ grid barrier (R7: acq_rel counter + gen poll) ---------- */
__device__ __forceinline__ void gbar() {
    __syncthreads();
    if (threadIdx.x == 0) {
        unsigned* cntp = &g_cnt;
        unsigned* genp = &g_gen;
        unsigned gen, prev;
        asm volatile("ld.global.relaxed.gpu.u32 %0, [%1];" : "=r"(gen) : "l"(genp));
        asm volatile("atom.global.acq_rel.gpu.add.u32 %0, [%1], 1;"
                     : "=r"(prev) : "l"(cntp) : "memory");
        if (prev == (unsigned)(RBLK-1)) {
            unsigned z = 0, ng = gen + 1;
            asm volatile("st.global.relaxed.gpu.u32 [%0], %1;" :: "l"(cntp), "r"(z) : "memory");
            asm volatile("st.global.release.gpu.u32 [%0], %1;" :: "l"(genp), "r"(ng) : "memory");
        } else {
            unsigned v;
            do {
                asm volatile("ld.global.acquire.gpu.u32 %0, [%1];" : "=r"(v) : "l"(genp) : "memory");
            } while (v == gen);
        }
    }
    __syncthreads();
}

__device__ __forceinline__ void bfly4(float4& a) {
#pragma unroll
    for (int d = 2; d < 32; d <<= 1) {
        a.x += __shfl_xor_sync(0xffffffffu, a.x, d);
        a.y += __shfl_xor_sync(0xffffffffu, a.y, d);
        a.z += __shfl_xor_sync(0xffffffffu, a.z, d);
        a.w += __shfl_xor_sync(0xffffffffu, a.w, d);
    }
}

__global__ void __launch_bounds__(RTHR) k_recurrent(
        const int* __restrict__ idx, const float* __restrict__ Wemb,
        const int* __restrict__ srcA, const float* __restrict__ GxA,
        const float* __restrict__ GyA, const float* __restrict__ GsA,
        float* __restrict__ sig_out)
{
    __shared__ int   s_n[CAP];
    __shared__ float s_gs[CAP], s_gx[CAP], s_gy[CAP], s_sig[CAP];
    __shared__ int   s_wcnt[NWARPS], s_wbase[NWARPS+1];

    const int tid  = threadIdx.x;
    const int wid  = tid >> 5;
    const int lane = tid & 31;
    const int h    = lane & 1;
    const int es   = lane >> 1;
    const int gtid = blockIdx.x*RTHR + tid;

    /* embed */
    for (int id = gtid; id < TT*N_NEURONS; id += RBLK*RTHR) {
        int t = id >> 12, n = id & (N_NEURONS-1);
        float v[8];
#pragma unroll
        for (int bb = 0; bb < 8; bb++)
            v[bb] = Wemb[(size_t)idx[bb*TT + t]*N_NEURONS + n];
        float4* o = (float4*)&g_Xall[(size_t)id*8];
        o[0] = make_float4(v[0], v[1], v[2], v[3]);
        o[1] = make_float4(v[4], v[5], v[6], v[7]);
    }

    /* two neurons per warp; bins padded to 32 */
    int nrn[NPW], grs[NPW], cnt[NPW], pc[NPW], lb[NPW];
#pragma unroll
    for (int i = 0; i < NPW; i++) {
        nrn[i] = blockIdx.x*NWARPS*NPW + wid*NPW + i;
        grs[i] = g_rowptr[nrn[i]];
        cnt[i] = g_rowptr[nrn[i]+1] - grs[i];
        pc[i]  = (cnt[i] + 31) & ~31;
    }
    if (lane == 0) s_wcnt[wid] = pc[0] + pc[1];
    __syncthreads();
    if (tid == 0) {
        int acc = 0;
        for (int w = 0; w < NWARPS; w++) { s_wbase[w] = acc; acc += s_wcnt[w]; }
        s_wbase[NWARPS] = acc;
    }
    __syncthreads();
    lb[0] = s_wbase[wid];
    lb[1] = lb[0] + pc[0];

    if (lane < NPW) {
        int c = cnt[lane], g0 = grs[lane], l0 = lb[lane];
        int lbuf[MAXB];
        for (int j = 0; j < c; j++) lbuf[j] = g_perm[g0 + j];
        for (int i = 1; i < c; i++) {
            int key = lbuf[i], j = i-1;
            while (j >= 0 && lbuf[j] > key) { lbuf[j+1] = lbuf[j]; j--; }
            lbuf[j+1] = key;
        }
        for (int j = 0; j < c; j++) s_n[l0 + j] = lbuf[j];
    }
    __syncwarp();
#pragma unroll
    for (int i = 0; i < NPW; i++) {
        for (int j = lane; j < pc[i]; j += 32) {
            int pos = lb[i] + j;
            if (j < cnt[i]) {
                int e = s_n[pos];
                g_perm[grs[i] + j] = e;
                s_n[pos]  = srcA[e];
                s_gs[pos] = GsA[e];
                s_gx[pos] = GxA[e];
                s_gy[pos] = GyA[e];
            } else {
                s_n[pos] = 0; s_gs[pos] = 0.f; s_gx[pos] = 0.f; s_gy[pos] = 0.f;
            }
            s_sig[pos] = 0.0f;
        }
    }
    gbar();

    /* y0 = X[:,0,:] */
#pragma unroll
    for (int i = 0; i < NPW; i++)
        if (lane < 2)
            *(float4*)&g_S[nrn[i]*16 + 8 + h*4] = *(const float4*)&g_Xall[nrn[i]*8 + h*4];
    gbar();

    const int it0 = pc[0] >> 4, it1 = pc[1] >> 4;
    const int itm = it0 > it1 ? it0 : it1;

    for (int t = 0; t < TT; t++) {
        const float* Xt = g_Xall + (size_t)t*NB;
        for (int layer = 0; layer < 2; layer++) {
            const float* xbase = (layer == 0) ? Xt : g_S;
            const int    xstr  = (layer == 0) ? 8 : 16;
            /* pass1: interleave both bins -> 2 independent gather groups */
            {
                float4 xn0 = *(const float4*)(xbase + (size_t)nrn[0]*xstr + h*4);
                float4 xn1 = *(const float4*)(xbase + (size_t)nrn[1]*xstr + h*4);
                float4 a0 = make_float4(0.f,0.f,0.f,0.f);
                float4 a1 = make_float4(0.f,0.f,0.f,0.f);
                for (int j = 0; j < itm; j++) {
                    int s0 = lb[0] + j*16 + es, s1 = lb[1] + j*16 + es;
                    int ns0 = 0, ns1 = 0; float sg0 = 0.f, sg1 = 0.f;
                    if (j < it0) { ns0 = s_n[s0]; sg0 = s_sig[s0]; }
                    if (j < it1) { ns1 = s_n[s1]; sg1 = s_sig[s1]; }
                    float4 xs0, ys0, xs1, ys1;
                    if (j < it0) {
                        xs0 = *(const float4*)(xbase + (size_t)ns0*xstr + h*4);
                        ys0 = *(const float4*)(&g_S[ns0*16 + 8 + h*4]);
                    }
                    if (j < it1) {
                        xs1 = *(const float4*)(xbase + (size_t)ns1*xstr + h*4);
                        ys1 = *(const float4*)(&g_S[ns1*16 + 8 + h*4]);
                    }
                    if (j < it0) {
                        float p = ys0.x*xn0.x + ys0.y*xn0.y + ys0.z*xn0.z + ys0.w*xn0.w;
                        p += __shfl_xor_sync(0xffffffffu, p, 1);
                        a0.x += xs0.x*sg0; a0.y += xs0.y*sg0;
                        a0.z += xs0.z*sg0; a0.w += xs0.w*sg0;
                        if (h == 0) s_sig[s0] = fmaf(p*0.125f, s_gs[s0], sg0) * DECAYF;
                    }
                    if (j < it1) {
                        float p = ys1.x*xn1.x + ys1.y*xn1.y + ys1.z*xn1.z + ys1.w*xn1.w;
                        p += __shfl_xor_sync(0xffffffffu, p, 1);
                        a1.x += xs1.x*sg1; a1.y += xs1.y*sg1;
                        a1.z += xs1.z*sg1; a1.w += xs1.w*sg1;
                        if (h == 0) s_sig[s1] = fmaf(p*0.125f, s_gs[s1], sg1) * DECAYF;
                    }
                }
                bfly4(a0); bfly4(a1);
                if (lane < 2) {
                    *(float4*)&g_A[nrn[0]*8 + h*4] = a0;
                    *(float4*)&g_A[nrn[1]*8 + h*4] = a1;
                }
            }
            gbar();
            /* pass2 */
            {
                float4 a0 = make_float4(0.f,0.f,0.f,0.f);
                float4 a1 = make_float4(0.f,0.f,0.f,0.f);
                for (int j = 0; j < itm; j++) {
                    int s0 = lb[0] + j*16 + es, s1 = lb[1] + j*16 + es;
                    int ns0 = 0, ns1 = 0; float gy0 = 0.f, gy1 = 0.f;
                    if (j < it0) { ns0 = s_n[s0]; gy0 = s_gy[s0]; }
                    if (j < it1) { ns1 = s_n[s1]; gy1 = s_gy[s1]; }
                    float4 v0, v1;
                    if (j < it0) v0 = *(const float4*)(&g_A[ns0*8 + h*4]);
                    if (j < it1) v1 = *(const float4*)(&g_A[ns1*8 + h*4]);
                    if (j < it0) {
                        v0.x = v0.x > 0.f ? v0.x : 0.f;  v0.y = v0.y > 0.f ? v0.y : 0.f;
                        v0.z = v0.z > 0.f ? v0.z : 0.f;  v0.w = v0.w > 0.f ? v0.w : 0.f;
                        a0.x += v0.x*gy0; a0.y += v0.y*gy0;
                        a0.z += v0.z*gy0; a0.w += v0.w*gy0;
                    }
                    if (j < it1) {
                        v1.x = v1.x > 0.f ? v1.x : 0.f;  v1.y = v1.y > 0.f ? v1.y : 0.f;
                        v1.z = v1.z > 0.f ? v1.z : 0.f;  v1.w = v1.w > 0.f ? v1.w : 0.f;
                        a1.x += v1.x*gy1; a1.y += v1.y*gy1;
                        a1.z += v1.z*gy1; a1.w += v1.w*gy1;
                    }
                }
                bfly4(a0); bfly4(a1);
                if (lane < 2) {
                    *(float4*)&g_S[nrn[0]*16 + 8 + h*4] = a0;
                    *(float4*)&g_S[nrn[1]*16 + 8 + h*4] = a1;
                }
            }
            gbar();
            /* pass3 */
            {
                float4 a0 = make_float4(0.f,0.f,0.f,0.f);
                float4 a1 = make_float4(0.f,0.f,0.f,0.f);
                for (int j = 0; j < itm; j++) {
                    int s0 = lb[0] + j*16 + es, s1 = lb[1] + j*16 + es;
                    int ns0 = 0, ns1 = 0; float gx0 = 0.f, gx1 = 0.f;
                    if (j < it0) { ns0 = s_n[s0]; gx0 = s_gx[s0]; }
                    if (j < it1) { ns1 = s_n[s1]; gx1 = s_gx[s1]; }
                    float4 v0, v1;
                    if (j < it0) v0 = *(const float4*)(&g_S[ns0*16 + 8 + h*4]);
                    if (j < it1) v1 = *(const float4*)(&g_S[ns1*16 + 8 + h*4]);
                    if (j < it0) {
                        a0.x += v0.x*gx0; a0.y += v0.y*gx0;
                        a0.z += v0.z*gx0; a0.w += v0.w*gx0;
                    }
                    if (j < it1) {
                        a1.x += v1.x*gx1; a1.y += v1.y*gx1;
                        a1.z += v1.z*gx1; a1.w += v1.w*gx1;
                    }
                }
                bfly4(a0); bfly4(a1);
                if (lane < 2) {
                    a0.x = a0.x > 0.f ? a0.x : 0.f;  a0.y = a0.y > 0.f ? a0.y : 0.f;
                    a0.z = a0.z > 0.f ? a0.z : 0.f;  a0.w = a0.w > 0.f ? a0.w : 0.f;
                    a1.x = a1.x > 0.f ? a1.x : 0.f;  a1.y = a1.y > 0.f ? a1.y : 0.f;
                    a1.z = a1.z > 0.f ? a1.z : 0.f;  a1.w = a1.w > 0.f ? a1.w : 0.f;
                    if (layer == 0) {
                        *(float4*)&g_S[nrn[0]*16 + h*4] = a0;
                        *(float4*)&g_S[nrn[1]*16 + h*4] = a1;
                    } else {
                        *(float4*)&g_xs[(size_t)t*NB + nrn[0]*8 + h*4] = a0;
                        *(float4*)&g_xs[(size_t)t*NB + nrn[1]*8 + h*4] = a1;
                    }
                }
            }
            if (layer == 0) gbar();
        }
    }

    if (sig_out)
#pragma unroll
        for (int i = 0; i < NPW; i++)
            for (int j = lane; j < cnt[i]; j += 32)
                sig_out[g_perm[grs[i] + j]] = s_sig[lb[i] + j];
}

/* ------------------ transpose + bf16 split of activations ------------------ */
__global__ void k_transpose() {
    int id = blockIdx.x*blockDim.x + threadIdx.x;
    if (id >= TT*N_NEURONS) return;
    int t = id >> 12, n = id & (N_NEURONS-1);
    const float4* p = (const float4*)&g_xs[(size_t)id*8];
    float4 v0 = p[0], v1 = p[1];
    float v[8] = {v0.x, v0.y, v0.z, v0.w, v1.x, v1.y, v1.z, v1.w};
#pragma unroll
    for (int bb = 0; bb < 8; bb++) {
        size_t o = (size_t)(bb*TT + t)*N_NEURONS + n;
        __nv_bfloat16 hh = __float2bfloat16_rn(v[bb]);
        g_Ahi[o] = hh;
        g_Alo[o] = __float2bfloat16_rn(v[bb] - __bfloat162float(hh));
    }
}

/* ------------------ mma.sync bf16 GEMM: 128x256 tile, warp 64x64 ----------- */
#define APITCH 40
#define ASTGB  (128*APITCH*2)
#define BSTGB  (256*APITCH*2)
#define NSTG   3
#define SMEM_GEMM (NSTG*(ASTGB + BSTGB))
#define NSTAGES_TOT 384

#define LDM4(r, a) asm volatile( \
    "ldmatrix.sync.aligned.m8n8.x4.shared.b16 {%0,%1,%2,%3}, [%4];" \
    : "=r"((r)[0]), "=r"((r)[1]), "=r"((r)[2]), "=r"((r)[3]) : "r"(a))

#define MMA16816(d, a, b0r, b1r) asm volatile( \
    "mma.sync.aligned.m16n8k16.row.col.f32.bf16.bf16.f32 " \
    "{%0,%1,%2,%3},{%4,%5,%6,%7},{%8,%9},{%0,%1,%2,%3};" \
    : "+f"((d)[0]), "+f"((d)[1]), "+f"((d)[2]), "+f"((d)[3]) \
    : "r"((a)[0]), "r"((a)[1]), "r"((a)[2]), "r"((a)[3]), "r"(b0r), "r"(b1r))

__global__ void __launch_bounds__(256, 1) k_gemm_mma(const float* __restrict__ bias,
                                                     float* __restrict__ out)
{
    extern __shared__ char smem[];
    const uint32_t sA = smem_u32(smem);
    const uint32_t sB = sA + NSTG*ASTGB;
    const int tid  = threadIdx.x;
    const int wid  = tid >> 5;
    const int lane = tid & 31;
    const int wm = wid & 1, wn = wid >> 1;
    const int m0 = blockIdx.x * 128;
    const int n0 = blockIdx.y * 256;

    float acc[4][8][4];
#pragma unroll
    for (int i = 0; i < 4; i++)
#pragma unroll
        for (int j = 0; j < 8; j++)
#pragma unroll
            for (int k = 0; k < 4; k++) acc[i][j][k] = 0.0f;

    auto load_stage = [&](int gs, int slot) {
        int seg = gs >> 7;
        int k0  = (gs & 127) << 5;
        const __nv_bfloat16* Ap = (seg == 1) ? g_Alo : g_Ahi;
        const __nv_bfloat16* Bp = (seg == 2) ? g_Wlo : g_Whi;
#pragma unroll
        for (int i = tid; i < 1536; i += 256) {
            if (i < 512) {
                int row = i >> 2, ch = i & 3;
                uint32_t da = sA + slot*ASTGB + (row*APITCH + ch*8)*2;
                const __nv_bfloat16* ga = Ap + (size_t)(m0 + row)*N_NEURONS + k0 + ch*8;
                asm volatile("cp.async.cg.shared.global [%0], [%1], 16;" :: "r"(da), "l"(ga) : "memory");
            } else {
                int i2 = i - 512;
                int row = i2 >> 2, ch = i2 & 3;
                uint32_t db = sB + slot*BSTGB + (row*APITCH + ch*8)*2;
                const __nv_bfloat16* gb = Bp + (size_t)(n0 + row)*N_NEURONS + k0 + ch*8;
                asm volatile("cp.async.cg.shared.global [%0], [%1], 16;" :: "r"(db), "l"(gb) : "memory");
            }
        }
        asm volatile("cp.async.commit_group;" ::: "memory");
    };

    load_stage(0, 0);
    load_stage(1, 1);

    for (int it = 0; it < NSTAGES_TOT; it++) {
        if (it + 2 < NSTAGES_TOT)
            asm volatile("cp.async.wait_group 1;" ::: "memory");
        else
            asm volatile("cp.async.wait_group 0;" ::: "memory");
        __syncthreads();
        if (it + 2 < NSTAGES_TOT)
            load_stage(it + 2, (it + 2) % NSTG);

        int slot = it % NSTG;
        uint32_t aB = sA + slot*ASTGB;
        uint32_t bB = sB + slot*BSTGB;
#pragma unroll
        for (int kk = 0; kk < 2; kk++) {
            uint32_t af[4][4], bf[4][4];
#pragma unroll
            for (int mi = 0; mi < 4; mi++) {
                uint32_t addr = aB + (uint32_t)(((wm*64 + mi*16 + (lane & 15))*APITCH
                                 + kk*16 + (lane >> 4)*8) * 2);
                LDM4(af[mi], addr);
            }
#pragma unroll
            for (int nh = 0; nh < 4; nh++) {
                int mat = lane >> 3;
                uint32_t addr = bB + (uint32_t)(((wn*64 + nh*16 + (lane & 7) + (mat >> 1)*8)*APITCH
                                 + kk*16 + (mat & 1)*8) * 2);
                LDM4(bf[nh], addr);
            }
#pragma unroll
            for (int mi = 0; mi < 4; mi++)
#pragma unroll
                for (int ni = 0; ni < 8; ni++)
                    MMA16816(acc[mi][ni], af[mi], bf[ni >> 1][(ni & 1)*2], bf[ni >> 1][(ni & 1)*2 + 1]);
        }
    }

    const int mb = m0 + wm*64;
    const int nb = n0 + wn*64;
#pragma unroll
    for (int ni = 0; ni < 8; ni++) {
        int c0 = nb + ni*8 + (lane & 3)*2;
        float bv0 = bias[c0], bv1 = bias[c0 + 1];
#pragma unroll
        for (int mi = 0; mi < 4; mi++) {
            int r0 = mb + mi*16 + (lane >> 2);
            float2 v0 = make_float2(acc[mi][ni][0] + bv0, acc[mi][ni][1] + bv1);
            float2 v1 = make_float2(acc[mi][ni][2] + bv0, acc[mi][ni][3] + bv1);
            *(float2*)&out[(size_t)r0*VOCAB + c0]       = v0;
            *(float2*)&out[(size_t)(r0 + 8)*VOCAB + c0] = v1;
        }
    }
}

/* ------------------ launch ------------------ */
extern "C" void kernel_launch(void* const* d_in, const int* in_sizes, int n_in,
                              void* d_out, int out_size) {
    const int*   idx  = (const int*)  d_in[0];
    const int*   src  = (const int*)  d_in[1];
    const int*   dst  = (const int*)  d_in[2];
    const float* Wemb = (const float*)d_in[3];
    const float* Gx   = (const float*)d_in[4];
    const float* Gy   = (const float*)d_in[5];
    const float* Gs   = (const float*)d_in[6];
    const float* Wout = (const float*)d_in[7];
    const float* bout = (const float*)d_in[8];
    float* out = (float*)d_out;

    long long btv = (long long)BB*TT*VOCAB;
    float* sig_out = ((long long)out_size >= btv + N_EDGES) ? (out + btv) : nullptr;

    static int smem_set = 0;
    if (!smem_set) {
        cudaFuncSetAttribute(k_gemm_mma, cudaFuncAttributeMaxDynamicSharedMemorySize, SMEM_GEMM);
        smem_set = 1;
    }

    k_hist   <<<512, 256>>>(dst);
    k_scan   <<<1, 1024>>>();
    k_scatter<<<512, 256>>>(dst);
    k_recurrent<<<RBLK, RTHR>>>(idx, Wemb, src, Gx, Gy, Gs, sig_out);  /* 4th: profiled */
    k_convW  <<<(VOCAB*N_NEURONS/4 + 255)/256, 256>>>(Wout);
    k_transpose<<<(TT*N_NEURONS)/256, 256>>>();
    dim3 gg(BB*TT/128, VOCAB/256);
    k_gemm_mma<<<gg, 256, SMEM_GEMM>>>(bout, out);
}

// round 16
// speedup vs baseline: 2.1118x; 1.1849x over previous
#include <cuda_runtime.h>
#include <cuda_bf16.h>
#include <cstdint>

#define N_NEURONS 4096
#define N_EDGES   131072
#define VOCAB     8192
#define BB        8
#define TT        128
#define NB        (N_NEURONS*BB)
#define DECAYF    0.99f

#define RBLK   128
#define RTHR   1024
#define NWARPS 32
#define CAP    2048
#define MAXB   128

/* ------------------ static device scratch ------------------ */
__device__ float g_Xall[TT*NB];
__device__ float g_xs  [TT*NB];
__device__ float g_S   [N_NEURONS*16];           /* x: +0..7, y: +8..15 */
__device__ float g_A[NB];
__device__ int   g_perm [N_EDGES];
__device__ int   g_counts[N_NEURONS];
__device__ int   g_cursor[N_NEURONS];
__device__ int   g_rowptr[N_NEURONS+1];
__device__ __nv_bfloat16 g_Ahi[BB*TT*N_NEURONS];
__device__ __nv_bfloat16 g_Alo[BB*TT*N_NEURONS];
__device__ __nv_bfloat16 g_Whi[VOCAB*N_NEURONS];
__device__ __nv_bfloat16 g_Wlo[VOCAB*N_NEURONS];

__device__ unsigned g_cnt = 0;
__device__ unsigned g_gen = 0;

__device__ __forceinline__ uint32_t smem_u32(const void* p) {
    uint32_t a;
    asm("{ .reg .u64 t; cvta.to.shared.u64 t, %1; cvt.u32.u64 %0, t; }" : "=r"(a) : "l"(p));
    return a;
}

/* ------------------ CSR preprocessing ------------------ */
__global__ void k_hist(const int* __restrict__ dst) {
    int e = blockIdx.x*blockDim.x + threadIdx.x;
    if (e < N_EDGES) atomicAdd(&g_counts[dst[e]], 1);
}
__global__ void k_scan() {
    __shared__ int sh[1024];
    int tid = threadIdx.x, base = tid*4;
    int v0 = g_counts[base+0], v1 = g_counts[base+1];
    int v2 = g_counts[base+2], v3 = g_counts[base+3];
    int s = v0+v1+v2+v3;
    sh[tid] = s; __syncthreads();
    for (int off = 1; off < 1024; off <<= 1) {
        int t = (tid >= off) ? sh[tid-off] : 0;
        __syncthreads(); sh[tid] += t; __syncthreads();
    }
    int excl = sh[tid] - s;
    g_rowptr[base+0] = excl; g_cursor[base+0] = excl; excl += v0;
    g_rowptr[base+1] = excl; g_cursor[base+1] = excl; excl += v1;
    g_rowptr[base+2] = excl; g_cursor[base+2] = excl; excl += v2;
    g_rowptr[base+3] = excl; g_cursor[base+3] = excl; excl += v3;
    if (tid == 1023) g_rowptr[N_NEURONS] = excl;
    g_counts[base+0]=0; g_counts[base+1]=0; g_counts[base+2]=0; g_counts[base+3]=0;
}
__global__ void k_scatter(const int* __restrict__ dst) {
    int e = blockIdx.x*blockDim.x + threadIdx.x;
    if (e < N_EDGES) { int p = atomicAdd(&g_cursor[dst[e]], 1); g_perm[p] = e; }
}

/* ------------------ W bf16 split ------------------ */
__global__ void k_convW(const float* __restrict__ W) {
    int i = blockIdx.x*blockDim.x + threadIdx.x;
    if (i >= VOCAB*N_NEURONS/4) return;
    float4 w = ((const float4*)W)[i];
    __nv_bfloat16 h[4], l[4];
    float v[4] = {w.x, w.y, w.z, w.w};
#pragma unroll
    for (int k = 0; k < 4; k++) {
        h[k] = __float2bfloat16_rn(v[k]);
        l[k] = __float2bfloat16_rn(v[k] - __bfloat162float(h[k]));
    }
    ((ushort4*)g_Whi)[i] = *(ushort4*)h;
    ((ushort4*)g_Wlo)[i] = *(ushort4*)l;
}

/* ------------------ grid barrier: counter arrival, target-gen release ------ */
/* Releaser path is atom.add -> st.release (no gen pre-load: one fewer serial
   L2 round trip than R12). Generation targets are monotone per call site. */
__device__ __forceinline__ void gbar(unsigned target) {
    __syncthreads();
    if (threadIdx.x == 0) {
        unsigned prev;
        asm volatile("atom.global.acq_rel.gpu.add.u32 %0, [%1], 1;"
                     : "=r"(prev) : "l"(&g_cnt) : "memory");
        if (prev == (unsigned)(RBLK-1)) {
            unsigned z = 0;
            asm volatile("st.global.relaxed.gpu.u32 [%0], %1;" :: "l"(&g_cnt), "r"(z) : "memory");
            asm volatile("st.global.release.gpu.u32 [%0], %1;" :: "l"(&g_gen), "r"(target) : "memory");
        } else {
            unsigned v;
            do {
                asm volatile("ld.global.acquire.gpu.u32 %0, [%1];" : "=r"(v) : "l"(&g_gen) : "memory");
            } while (v < target);
        }
    }
    __syncthreads();
}

/* reset barrier state so graph replays start clean */
__global__ void k_rstbar() {
    if (threadIdx.x == 0) { g_cnt = 0; g_gen = 0; }
}

__device__ __forceinline__ void bfly4(float4& a) {
#pragma unroll
    for (int d = 2; d < 32; d <<= 1) {
        a.x += __shfl_xor_sync(0xffffffffu, a.x, d);
        a.y += __shfl_xor_sync(0xffffffffu, a.y, d);
        a.z += __shfl_xor_sync(0xffffffffu, a.z, d);
        a.w += __shfl_xor_sync(0xffffffffu, a.w, d);
    }
}

__global__ void __launch_bounds__(RTHR) k_recurrent(
        const int* __restrict__ idx, const float* __restrict__ Wemb,
        const int* __restrict__ srcA, const float* __restrict__ GxA,
        const float* __restrict__ GyA, const float* __restrict__ GsA,
        float* __restrict__ sig_out)
{
    __shared__ int   s_n[CAP];
    __shared__ float s_gs[CAP], s_gx[CAP], s_gy[CAP], s_sig[CAP];
    __shared__ int   s_wcnt[NWARPS], s_wbase[NWARPS+1];

    const int tid  = threadIdx.x;
    const int wid  = tid >> 5;
    const int lane = tid & 31;
    const int nrn  = blockIdx.x*NWARPS + wid;
    const int h    = lane & 1;
    const int es   = lane >> 1;
    const int gtid = blockIdx.x*RTHR + tid;
    unsigned bar = 0;

    /* embed */
    for (int id = gtid; id < TT*N_NEURONS; id += RBLK*RTHR) {
        int t = id >> 12, n = id & (N_NEURONS-1);
        float v[8];
#pragma unroll
        for (int bb = 0; bb < 8; bb++)
            v[bb] = Wemb[(size_t)idx[bb*TT + t]*N_NEURONS + n];
        float4* o = (float4*)&g_Xall[(size_t)id*8];
        o[0] = make_float4(v[0], v[1], v[2], v[3]);
        o[1] = make_float4(v[4], v[5], v[6], v[7]);
    }

    /* stage edges (padded to 32 per neuron) */
    const int grs = g_rowptr[nrn];
    const int cnt = g_rowptr[nrn+1] - grs;
    const int pc  = (cnt + 31) & ~31;
    if (lane == 0) s_wcnt[wid] = pc;
    __syncthreads();
    if (tid == 0) {
        int acc = 0;
        for (int w = 0; w < NWARPS; w++) { s_wbase[w] = acc; acc += s_wcnt[w]; }
        s_wbase[NWARPS] = acc;
    }
    __syncthreads();
    const int lb = s_wbase[wid];

    if (lane == 0) {
        int lbuf[MAXB];
        for (int j = 0; j < cnt; j++) lbuf[j] = g_perm[grs + j];
        for (int i = 1; i < cnt; i++) {
            int key = lbuf[i], j = i-1;
            while (j >= 0 && lbuf[j] > key) { lbuf[j+1] = lbuf[j]; j--; }
            lbuf[j+1] = key;
        }
        for (int j = 0; j < cnt; j++) s_n[lb + j] = lbuf[j];
    }
    __syncwarp();
    for (int j = lane; j < pc; j += 32) {
        int pos = lb + j;
        if (j < cnt) {
            int e = s_n[pos];
            g_perm[grs + j] = e;
            s_n[pos]  = srcA[e];
            s_gs[pos] = GsA[e];
            s_gx[pos] = GxA[e];
            s_gy[pos] = GyA[e];
        } else {
            s_n[pos] = 0; s_gs[pos] = 0.f; s_gx[pos] = 0.f; s_gy[pos] = 0.f;
        }
        s_sig[pos] = 0.0f;
    }
    gbar(++bar);

    /* y0 = X[:,0,:] */
    if (lane < 2)
        *(float4*)&g_S[nrn*16 + 8 + h*4] = *(const float4*)&g_Xall[nrn*8 + h*4];
    gbar(++bar);

    for (int t = 0; t < TT; t++) {
        const float* Xt = g_Xall + (size_t)t*NB;
        for (int layer = 0; layer < 2; layer++) {
            const float* xbase = (layer == 0) ? Xt : g_S;
            const int    xstr  = (layer == 0) ? 8 : 16;
            /* pass1: A[n] = sum x[src]*sigma(old) ; sigma hebbian update */
            {
                float4 xn4 = *(const float4*)(xbase + (size_t)nrn*xstr + h*4);
                float4 acc = make_float4(0.f, 0.f, 0.f, 0.f);
                for (int j0 = 0; j0 < pc; j0 += 16) {
                    int   slot = lb + j0 + es;
                    int   ns   = s_n[slot];
                    float sg   = s_sig[slot];
                    float4 xs4 = *(const float4*)(xbase + (size_t)ns*xstr + h*4);
                    float4 ys4 = *(const float4*)(&g_S[ns*16 + 8 + h*4]);
                    float p = ys4.x*xn4.x + ys4.y*xn4.y + ys4.z*xn4.z + ys4.w*xn4.w;
                    p += __shfl_xor_sync(0xffffffffu, p, 1);
                    acc.x += xs4.x*sg; acc.y += xs4.y*sg;
                    acc.z += xs4.z*sg; acc.w += xs4.w*sg;
                    if (h == 0)
                        s_sig[slot] = fmaf(p*0.125f, s_gs[slot], sg) * DECAYF;
                }
                bfly4(acc);
                if (lane < 2) *(float4*)&g_A[nrn*8 + h*4] = acc;
            }
            gbar(++bar);
            /* pass2: y[n] = sum relu(A[src])*Gy */
            {
                float4 acc = make_float4(0.f, 0.f, 0.f, 0.f);
                for (int j0 = 0; j0 < pc; j0 += 16) {
                    int   slot = lb + j0 + es;
                    int   ns   = s_n[slot];
                    float gy   = s_gy[slot];
                    float4 a4  = *(const float4*)(&g_A[ns*8 + h*4]);
                    a4.x = a4.x > 0.f ? a4.x : 0.f;  a4.y = a4.y > 0.f ? a4.y : 0.f;
                    a4.z = a4.z > 0.f ? a4.z : 0.f;  a4.w = a4.w > 0.f ? a4.w : 0.f;
                    acc.x += a4.x*gy; acc.y += a4.y*gy;
                    acc.z += a4.z*gy; acc.w += a4.w*gy;
                }
                bfly4(acc);
                if (lane < 2) *(float4*)&g_S[nrn*16 + 8 + h*4] = acc;
            }
            gbar(++bar);
            /* pass3: x[n] = relu(sum y[src]*Gx) */
            {
                float4 acc = make_float4(0.f, 0.f, 0.f, 0.f);
                for (int j0 = 0; j0 < pc; j0 += 16) {
                    int   slot = lb + j0 + es;
                    int   ns   = s_n[slot];
                    float gx   = s_gx[slot];
                    float4 y4  = *(const float4*)(&g_S[ns*16 + 8 + h*4]);
                    acc.x += y4.x*gx; acc.y += y4.y*gx;
                    acc.z += y4.z*gx; acc.w += y4.w*gx;
                }
                bfly4(acc);
                if (lane < 2) {
                    acc.x = acc.x > 0.f ? acc.x : 0.f;  acc.y = acc.y > 0.f ? acc.y : 0.f;
                    acc.z = acc.z > 0.f ? acc.z : 0.f;  acc.w = acc.w > 0.f ? acc.w : 0.f;
                    if (layer == 0) *(float4*)&g_S[nrn*16 + h*4] = acc;
                    else            *(float4*)&g_xs[(size_t)t*NB + nrn*8 + h*4] = acc;
                }
            }
            if (layer == 0) gbar(++bar);
        }
    }

    if (sig_out)
        for (int j = lane; j < cnt; j += 32)
            sig_out[g_perm[grs + j]] = s_sig[lb + j];
}

/* ------------------ transpose + bf16 split of activations ------------------ */
__global__ void k_transpose() {
    int id = blockIdx.x*blockDim.x + threadIdx.x;
    if (id >= TT*N_NEURONS) return;
    int t = id >> 12, n = id & (N_NEURONS-1);
    const float4* p = (const float4*)&g_xs[(size_t)id*8];
    float4 v0 = p[0], v1 = p[1];
    float v[8] = {v0.x, v0.y, v0.z, v0.w, v1.x, v1.y, v1.z, v1.w};
#pragma unroll
    for (int bb = 0; bb < 8; bb++) {
        size_t o = (size_t)(bb*TT + t)*N_NEURONS + n;
        __nv_bfloat16 hh = __float2bfloat16_rn(v[bb]);
        g_Ahi[o] = hh;
        g_Alo[o] = __float2bfloat16_rn(v[bb] - __bfloat162float(hh));
    }
}

/* ------------------ mma.sync bf16 GEMM: 128x256 tile, warp 64x64 ----------- */
#define APITCH 40
#define ASTGB  (128*APITCH*2)
#define BSTGB  (256*APITCH*2)
#define NSTG   3
#define SMEM_GEMM (NSTG*(ASTGB + BSTGB))
#define NSTAGES_TOT 384

#define LDM4(r, a) asm volatile( \
    "ldmatrix.sync.aligned.m8n8.x4.shared.b16 {%0,%1,%2,%3}, [%4];" \
    : "=r"((r)[0]), "=r"((r)[1]), "=r"((r)[2]), "=r"((r)[3]) : "r"(a))

#define MMA16816(d, a, b0r, b1r) asm volatile( \
    "mma.sync.aligned.m16n8k16.row.col.f32.bf16.bf16.f32 " \
    "{%0,%1,%2,%3},{%4,%5,%6,%7},{%8,%9},{%0,%1,%2,%3};" \
    : "+f"((d)[0]), "+f"((d)[1]), "+f"((d)[2]), "+f"((d)[3]) \
    : "r"((a)[0]), "r"((a)[1]), "r"((a)[2]), "r"((a)[3]), "r"(b0r), "r"(b1r))

__global__ void __launch_bounds__(256, 1) k_gemm_mma(const float* __restrict__ bias,
                                                     float* __restrict__ out)
{
    extern __shared__ char smem[];
    const uint32_t sA = smem_u32(smem);
    const uint32_t sB = sA + NSTG*ASTGB;
    const int tid  = threadIdx.x;
    const int wid  = tid >> 5;
    const int lane = tid & 31;
    const int wm = wid & 1, wn = wid >> 1;
    const int m0 = blockIdx.x * 128;
    const int n0 = blockIdx.y * 256;

    float acc[4][8][4];
#pragma unroll
    for (int i = 0; i < 4; i++)
#pragma unroll
        for (int j = 0; j < 8; j++)
#pragma unroll
            for (int k = 0; k < 4; k++) acc[i][j][k] = 0.0f;

    auto load_stage = [&](int gs, int slot) {
        int seg = gs >> 7;
        int k0  = (gs & 127) << 5;
        const __nv_bfloat16* Ap = (seg == 1) ? g_Alo : g_Ahi;
        const __nv_bfloat16* Bp = (seg == 2) ? g_Wlo : g_Whi;
#pragma unroll
        for (int i = tid; i < 1536; i += 256) {
            if (i < 512) {
                int row = i >> 2, ch = i & 3;
                uint32_t da = sA + slot*ASTGB + (row*APITCH + ch*8)*2;
                const __nv_bfloat16* ga = Ap + (size_t)(m0 + row)*N_NEURONS + k0 + ch*8;
                asm volatile("cp.async.cg.shared.global [%0], [%1], 16;" :: "r"(da), "l"(ga) : "memory");
            } else {
                int i2 = i - 512;
                int row = i2 >> 2, ch = i2 & 3;
                uint32_t db = sB + slot*BSTGB + (row*APITCH + ch*8)*2;
                const __nv_bfloat16* gb = Bp + (size_t)(n0 + row)*N_NEURONS + k0 + ch*8;
                asm volatile("cp.async.cg.shared.global [%0], [%1], 16;" :: "r"(db), "l"(gb) : "memory");
            }
        }
        asm volatile("cp.async.commit_group;" ::: "memory");
    };

    load_stage(0, 0);
    load_stage(1, 1);

    for (int it = 0; it < NSTAGES_TOT; it++) {
        if (it + 2 < NSTAGES_TOT)
            asm volatile("cp.async.wait_group 1;" ::: "memory");
        else
            asm volatile("cp.async.wait_group 0;" ::: "memory");
        __syncthreads();
        if (it + 2 < NSTAGES_TOT)
            load_stage(it + 2, (it + 2) % NSTG);

        int slot = it % NSTG;
        uint32_t aB = sA + slot*ASTGB;
        uint32_t bB = sB + slot*BSTGB;
#pragma unroll
        for (int kk = 0; kk < 2; kk++) {
            uint32_t af[4][4], bf[4][4];
#pragma unroll
            for (int mi = 0; mi < 4; mi++) {
                uint32_t addr = aB + (uint32_t)(((wm*64 + mi*16 + (lane & 15))*APITCH
                                 + kk*16 + (lane >> 4)*8) * 2);
                LDM4(af[mi], addr);
            }
#pragma unroll
            for (int nh = 0; nh < 4; nh++) {
                int mat = lane >> 3;
                uint32_t addr = bB + (uint32_t)(((wn*64 + nh*16 + (lane & 7) + (mat >> 1)*8)*APITCH
                                 + kk*16 + (mat & 1)*8) * 2);
                LDM4(bf[nh], addr);
            }
#pragma unroll
            for (int mi = 0; mi < 4; mi++)
#pragma unroll
                for (int ni = 0; ni < 8; ni++)
                    MMA16816(acc[mi][ni], af[mi], bf[ni >> 1][(ni & 1)*2], bf[ni >> 1][(ni & 1)*2 + 1]);
        }
    }

    const int mb = m0 + wm*64;
    const int nb = n0 + wn*64;
#pragma unroll
    for (int ni = 0; ni < 8; ni++) {
        int c0 = nb + ni*8 + (lane & 3)*2;
        float bv0 = bias[c0], bv1 = bias[c0 + 1];
#pragma unroll
        for (int mi = 0; mi < 4; mi++) {
            int r0 = mb + mi*16 + (lane >> 2);
            float2 v0 = make_float2(acc[mi][ni][0] + bv0, acc[mi][ni][1] + bv1);
            float2 v1 = make_float2(acc[mi][ni][2] + bv0, acc[mi][ni][3] + bv1);
            *(float2*)&out[(size_t)r0*VOCAB + c0]       = v0;
            *(float2*)&out[(size_t)(r0 + 8)*VOCAB + c0] = v1;
        }
    }
}

/* ------------------ launch ------------------ */
extern "C" void kernel_launch(void* const* d_in, const int* in_sizes, int n_in,
                              void* d_out, int out_size) {
    const int*   idx  = (const int*)  d_in[0];
    const int*   src  = (const int*)  d_in[1];
    const int*   dst  = (const int*)  d_in[2];
    const float* Wemb = (const float*)d_in[3];
    const float* Gx   = (const float*)d_in[4];
    const float* Gy   = (const float*)d_in[5];
    const float* Gs   = (const float*)d_in[6];
    const float* Wout = (const float*)d_in[7];
    const float* bout = (const float*)d_in[8];
    float* out = (float*)d_out;

    long long btv = (long long)BB*TT*VOCAB;
    float* sig_out = ((long long)out_size >= btv + N_EDGES) ? (out + btv) : nullptr;

    static int smem_set = 0;
    if (!smem_set) {
        cudaFuncSetAttribute(k_gemm_mma, cudaFuncAttributeMaxDynamicSharedMemorySize, SMEM_GEMM);
        smem_set = 1;
    }

    k_hist   <<<512, 256>>>(dst);
    k_scan   <<<1, 1024>>>();
    k_scatter<<<512, 256>>>(dst);
    k_recurrent<<<RBLK, RTHR>>>(idx, Wemb, src, Gx, Gy, Gs, sig_out);  /* 4th: profiled */
    k_rstbar <<<1, 32>>>();
    k_convW  <<<(VOCAB*N_NEURONS/4 + 255)/256, 256>>>(Wout);
    k_transpose<<<(TT*N_NEURONS)/256, 256>>>();
    dim3 gg(BB*TT/128, VOCAB/256);
    k_gemm_mma<<<gg, 256, SMEM_GEMM>>>(bout, out);
}